// round 16
// baseline (speedup 1.0000x reference)
#include <cuda_runtime.h>
#include <math.h>

#define HH   192
#define WW   192
#define CIN  64
#define SHC  8
#define NB   8
#define NPIX (HH*WW)

typedef unsigned long long ull;

// h = gelu(conv1(x)), PIXEL-MAJOR: [b][pix][8 sh-channels] (9.4 MB)
__device__ float g_h[(size_t)NB * NPIX * SHC];

__device__ __forceinline__ float fsqrt_approx(float v) {
    float r; asm("sqrt.approx.f32 %0, %1;" : "=f"(r) : "f"(v)); return r;
}
__device__ __forceinline__ unsigned bf16pack(float lo, float hi) {
    unsigned r; asm("cvt.rn.bf16x2.f32 %0, %1, %2;" : "=r"(r) : "f"(hi), "f"(lo)); return r;
}
// ---- f32x2 packed helpers (fuse) ----
__device__ __forceinline__ ull ffma2(ull a, ull b, ull c) {
    ull r; asm("fma.rn.f32x2 %0, %1, %2, %3;" : "=l"(r) : "l"(a), "l"(b), "l"(c)); return r;
}
__device__ __forceinline__ ull dup2(float v) {
    ull r; asm("mov.b64 %0, {%1, %1};" : "=l"(r) : "f"(v)); return r;
}
__device__ __forceinline__ ull pack2(float lo, float hi) {
    ull r; asm("mov.b64 %0, {%1, %2};" : "=l"(r) : "f"(lo), "f"(hi)); return r;
}
__device__ __forceinline__ void unpack2(ull v, float& lo, float& hi) {
    asm("mov.b64 {%0, %1}, %2;" : "=f"(lo), "=f"(hi) : "l"(v));
}

// ---------------------------------------------------------------------------
// Kernel 1: 3x3 SAME conv (64 -> 8) + exact GELU via bf16 m16n8k16 mma.
// R16: prepack eliminated — staging converts fp32 -> bf16x2 in-flight
// (LDG even/odd plane + cvt.rn.bf16x2 + STS), each x element read ONCE.
// Tile 64x16, 256 thr, 288 blocks = 2 blocks/SM: one block's LDG staging
// overlaps the co-resident block's LDS/HMMA phase.
// Fragment mapping identical to validated R15. PS=1192 (== 8 mod 32).
// ---------------------------------------------------------------------------
#define PS     1192                    // pair-plane stride in words (8 mod 32)
#define PROWS  18                      // 16 + 2 halo
#define PCOLS  66                      // 64 + 2 halo
#define PLANES 8                       // 8 ic-pair planes per icg (= 16 ics)
#define DBUF   (PLANES * PS)           // 9536 words
#define NWSM   (4 * 9 * 8 * 8)         // [icg][tap][kpair][oc] words = 2304
#define CONV_SMEM ((DBUF + NWSM) * 4)  // 47,360 B
#define CTH    256

__global__ void __launch_bounds__(CTH, 2)
conv1_gelu_kernel(const float* __restrict__ x, const float* __restrict__ w1)
{
    extern __shared__ unsigned sm_u[];
    unsigned* dsm = sm_u;              // [PLANES*PS] bf16x2 words (single buffer)
    unsigned* wsm = sm_u + DBUF;       // [icg][tap][kpair][oc] bf16x2 words

    const int tid   = threadIdx.x;
    const int b     = blockIdx.z;
    const int tileX = blockIdx.x * 64;
    const int tileY = blockIdx.y * 16;

    // weights: word[icg][tap][kp][oc] = (W[ic=icg*16+2kp][tap][oc], W[ic+1][...])
    for (int i = tid; i < NWSM; i += CTH) {
        int oc  = i & 7;
        int kp  = (i >> 3) & 7;
        int tap = (i >> 6) % 9;
        int icg = i / (9 * 64);
        int ic  = icg * 16 + 2 * kp;
        wsm[i] = bf16pack(w1[(oc * CIN + ic) * 9 + tap],
                          w1[(oc * CIN + ic + 1) * 9 + tap]);
    }

    const float* xb = x + (size_t)b * CIN * NPIX;

    const int lane = tid & 31;
    const int wrp  = tid >> 5;        // 0..7: rows 2*wrp..2*wrp+1
    const int g    = lane >> 2;       // 0..7
    const int t4   = lane & 3;        // 0..3

    float acc[8][4];
    #pragma unroll
    for (int m = 0; m < 8; m++)
        #pragma unroll
        for (int e = 0; e < 4; e++) acc[m][e] = 0.f;

    for (int icg = 0; icg < 4; icg++) {
        __syncthreads();               // previous mma done reading dsm

        // stage icg: LDG fp32 (even,odd ic planes) -> bf16x2 word -> STS
        #pragma unroll 1
        for (int i = tid; i < PLANES * PROWS * PCOLS; i += CTH) {
            int p   = i / (PROWS * PCOLS);
            int rem = i - p * (PROWS * PCOLS);
            int r   = rem / PCOLS;
            int cc  = rem - r * PCOLS;
            int gy  = tileY - 1 + r;
            int gx  = tileX - 1 + cc;
            unsigned w = 0u;
            if ((unsigned)gy < (unsigned)HH && (unsigned)gx < (unsigned)WW) {
                const float* e = xb + (size_t)(icg * 16 + 2 * p) * NPIX + gy * WW + gx;
                float f0 = __ldg(e);
                float f1 = __ldg(e + NPIX);
                w = bf16pack(f0, f1);
            }
            dsm[p * PS + r * PCOLS + cc] = w;
        }
        __syncthreads();               // staged data visible

        const unsigned* A0 = dsm + t4 * PS + g;          // kpairs t4
        const unsigned* A1 = A0 + 4 * PS;                // kpairs t4+4
        const unsigned* wg = wsm + (icg * 9) * 64;

        #pragma unroll
        for (int tap = 0; tap < 9; tap++) {
            const int ky = tap / 3, kx = tap % 3;
            unsigned b0 = wg[tap * 64 + t4 * 8 + g];
            unsigned b1 = wg[tap * 64 + (t4 + 4) * 8 + g];

            #pragma unroll
            for (int r = 0; r < 2; r++) {
                const int rowoff = (2 * wrp + r + ky) * PCOLS + kx;
                #pragma unroll
                for (int q = 0; q < 4; q++) {
                    const int off = rowoff + 16 * q;
                    unsigned a0 = A0[off];
                    unsigned a1 = A0[off + 8];
                    unsigned a2 = A1[off];
                    unsigned a3 = A1[off + 8];
                    float* d = acc[r * 4 + q];
                    asm volatile(
                        "mma.sync.aligned.m16n8k16.row.col.f32.bf16.bf16.f32 "
                        "{%0,%1,%2,%3}, {%4,%5,%6,%7}, {%8,%9}, {%0,%1,%2,%3};"
                        : "+f"(d[0]), "+f"(d[1]), "+f"(d[2]), "+f"(d[3])
                        : "r"(a0), "r"(a1), "r"(a2), "r"(a3), "r"(b0), "r"(b1));
                }
            }
        }
    }

    // Epilogue: thread (g,t4) holds px x0+g (oc 2t4,2t4+1) and px x0+g+8.
    const float inv_sqrt2 = 0.70710678118654752f;
    #pragma unroll
    for (int r = 0; r < 2; r++) {
        const int gy = tileY + 2 * wrp + r;
        #pragma unroll
        for (int q = 0; q < 4; q++) {
            const float* d = acc[r * 4 + q];
            const int px0 = tileX + 16 * q + g;
            float* hp0 = g_h + ((size_t)b * NPIX + (size_t)gy * WW + px0) * SHC + 2 * t4;
            float2 o;
            float u;
            u = d[0]; o.x = 0.5f * u * (1.f + erff(u * inv_sqrt2));
            u = d[1]; o.y = 0.5f * u * (1.f + erff(u * inv_sqrt2));
            *reinterpret_cast<float2*>(hp0) = o;
            u = d[2]; o.x = 0.5f * u * (1.f + erff(u * inv_sqrt2));
            u = d[3]; o.y = 0.5f * u * (1.f + erff(u * inv_sqrt2));
            *reinterpret_cast<float2*>(hp0 + 8 * SHC) = o;
        }
    }
}

// ---------------------------------------------------------------------------
// Kernel 2: EXACT R10/R12 fuse (measured best: 119.2us). PROTECTED.
// ---------------------------------------------------------------------------
#define PAD 200

__global__ void __launch_bounds__(768, 1)
fuse_kernel(const float* __restrict__ x, const float* __restrict__ w2,
            const float* __restrict__ b2, const float* __restrict__ lsc,
            float* __restrict__ out)
{
    extern __shared__ float img[];           // NPIX + PAD floats
    const int tid  = threadIdx.x;
    const int bc   = blockIdx.x >> 1;
    const int half = blockIdx.x & 1;
    const int c    = bc & 63;

    const float4* src  = reinterpret_cast<const float4*>(x + (size_t)bc * NPIX);
    float4*       dst4 = reinterpret_cast<float4*>(img);
    #pragma unroll 4
    for (int i = tid; i < NPIX / 4; i += 768) dst4[i] = src[i];
    if (tid < PAD / 4)
        reinterpret_cast<float4*>(img + NPIX)[tid] = make_float4(0.f, 0.f, 0.f, 0.f);

    const float PXS = 9.55f;                 // 0.1 * 95.5
    ull w01[8], w23[8];
    #pragma unroll
    for (int s = 0; s < 8; s++) {
        w01[s] = pack2(__ldg(&w2[(4 * c + 0) * 8 + s]),
                       __ldg(&w2[(4 * c + 1) * 8 + s]) * PXS);
        w23[s] = pack2(__ldg(&w2[(4 * c + 2) * 8 + s]) * PXS,
                       __ldg(&w2[(4 * c + 3) * 8 + s]));
    }
    const ull bias01 = pack2(__ldg(&b2[4 * c + 0]), __ldg(&b2[4 * c + 1]) * PXS);
    const ull bias23 = pack2(__ldg(&b2[4 * c + 2]) * PXS, __ldg(&b2[4 * c + 3]));

    const float esc   = expf(__ldg(lsc));
    const float esc4  = 0.25f * esc;
    const float esc01 = 0.1f  * esc;
    const float* hb = g_h + (size_t)(bc >> 6) * NPIX * SHC;
    float* ob = out + (size_t)bc * NPIX;

    const float step = 2.0f / 191.0f;

    const int rphase = tid / 192;            // 0..3
    const int xi     = tid - rphase * 192;   // 0..191
    const float gxpix = (fmaf((float)xi, step, -1.0f) + 1.0f) * 95.5f;
    const int y0     = half * 96 + rphase;

    __syncthreads();

    #pragma unroll 1
    for (int k = 0; k < 12; k++) {
        const int yiA  = y0 + 4 * k;
        const int idxA = yiA * WW + xi;

        int   idx[2]   = { idxA, idxA + 48 * WW };
        float gypix[2] = { (fmaf((float)yiA,        step, -1.0f) + 1.0f) * 95.5f,
                           (fmaf((float)(yiA + 48), step, -1.0f) + 1.0f) * 95.5f };

        float4 h0[2], h1[2];
        #pragma unroll
        for (int j = 0; j < 2; j++) {
            const float4* hp = reinterpret_cast<const float4*>(hb + (size_t)idx[j] * SHC);
            h0[j] = hp[0];
            h1[j] = hp[1];
        }

        float s95[2], dxp[2], dyp[2], cvv[2];
        #pragma unroll
        for (int j = 0; j < 2; j++) {
            ull a01 = bias01, a23 = bias23;
            ull d;
            d = dup2(h0[j].x); a01 = ffma2(d, w01[0], a01); a23 = ffma2(d, w23[0], a23);
            d = dup2(h0[j].y); a01 = ffma2(d, w01[1], a01); a23 = ffma2(d, w23[1], a23);
            d = dup2(h0[j].z); a01 = ffma2(d, w01[2], a01); a23 = ffma2(d, w23[2], a23);
            d = dup2(h0[j].w); a01 = ffma2(d, w01[3], a01); a23 = ffma2(d, w23[3], a23);
            d = dup2(h1[j].x); a01 = ffma2(d, w01[4], a01); a23 = ffma2(d, w23[4], a23);
            d = dup2(h1[j].y); a01 = ffma2(d, w01[5], a01); a23 = ffma2(d, w23[5], a23);
            d = dup2(h1[j].z); a01 = ffma2(d, w01[6], a01); a23 = ffma2(d, w23[6], a23);
            d = dup2(h1[j].w); a01 = ffma2(d, w01[7], a01); a23 = ffma2(d, w23[7], a23);
            float a, bxp, byp, cv;
            unpack2(a01, a, bxp);
            unpack2(a23, byp, cv);

            float t  = __expf(-fabsf(a));
            float sp = fmaxf(a, 0.f) + __logf(1.0f + t);
            s95[j] = fsqrt_approx(fmaf(sp, 912.025f, 9.12025e-5f));
            dxp[j] = bxp;
            dyp[j] = byp;
            cvv[j] = fminf(fmaxf(cv, -5.f), 5.f);
        }

        #pragma unroll
        for (int j = 0; j < 2; j++) {
            float px3  = gxpix    + dxp[j];
            float px1  = px3      + s95[j];
            float px2  = px3      - s95[j];
            float py12 = gypix[j] + dyp[j];
            float py3  = py12     + s95[j];
            float py4  = py12     - s95[j];

            float pyc = fminf(fmaxf(py12, 0.f), 191.f);
            float y0f = floorf(pyc);
            float wy  = pyc - y0f;

            float pxc1 = fminf(fmaxf(px1, 0.f), 191.f);
            float x0f1 = floorf(pxc1);
            float wx1  = pxc1 - x0f1;
            int   o1   = (int)fmaf(y0f, 192.f, x0f1);
            float v00 = img[o1],       v01 = img[o1 + 1];
            float v10 = img[o1 + 192], v11 = img[o1 + 193];
            float top = fmaf(v01 - v00, wx1, v00);
            float bot = fmaf(v11 - v10, wx1, v10);
            float u1  = fmaf(bot - top, wy, top);

            float pxc2 = fminf(fmaxf(px2, 0.f), 191.f);
            float x0f2 = floorf(pxc2);
            float wx2  = pxc2 - x0f2;
            int   o2   = (int)fmaf(y0f, 192.f, x0f2);
            v00 = img[o2];       v01 = img[o2 + 1];
            v10 = img[o2 + 192]; v11 = img[o2 + 193];
            top = fmaf(v01 - v00, wx2, v00);
            bot = fmaf(v11 - v10, wx2, v10);
            float u2 = fmaf(bot - top, wy, top);

            float pxc3 = fminf(fmaxf(px3, 0.f), 191.f);
            float x0f3 = floorf(pxc3);
            float wx3  = pxc3 - x0f3;

            float pyc3 = fminf(fmaxf(py3, 0.f), 191.f);
            float y0f3 = floorf(pyc3);
            float wy3  = pyc3 - y0f3;
            int   o3   = (int)fmaf(y0f3, 192.f, x0f3);
            v00 = img[o3];       v01 = img[o3 + 1];
            v10 = img[o3 + 192]; v11 = img[o3 + 193];
            top = fmaf(v01 - v00, wx3, v00);
            bot = fmaf(v11 - v10, wx3, v10);
            float u3 = fmaf(bot - top, wy3, top);

            float pyc4 = fminf(fmaxf(py4, 0.f), 191.f);
            float y0f4 = floorf(pyc4);
            float wy4  = pyc4 - y0f4;
            int   o4   = (int)fmaf(y0f4, 192.f, x0f3);
            v00 = img[o4];       v01 = img[o4 + 1];
            v10 = img[o4 + 192]; v11 = img[o4 + 193];
            top = fmaf(v01 - v00, wx3, v00);
            bot = fmaf(v11 - v10, wx3, v10);
            float u4 = fmaf(bot - top, wy4, top);

            float usum = (u1 + u2) + (u3 + u4);
            float xv   = img[idx[j]];
            ob[idx[j]] = fmaf(esc4, usum, esc01 * cvv[j] * xv);
        }
    }
}

// ---------------------------------------------------------------------------
extern "C" void kernel_launch(void* const* d_in, const int* in_sizes, int n_in,
                              void* d_out, int out_size)
{
    const float *x = nullptr, *w1 = nullptr, *w2 = nullptr, *b2 = nullptr, *ls = nullptr;
    for (int i = 0; i < n_in; i++) {
        switch (in_sizes[i]) {
            case NB * CIN * NPIX: x  = (const float*)d_in[i]; break;
            case SHC * CIN * 9:   w1 = (const float*)d_in[i]; break;
            case 4 * CIN * SHC:   w2 = (const float*)d_in[i]; break;
            case 4 * CIN:         b2 = (const float*)d_in[i]; break;
            case 1:               ls = (const float*)d_in[i]; break;
            default: break;
        }
    }

    // conv via bf16 mma, fused fp32->bf16 staging (no prepack)
    dim3 g1(3, 12, NB);                      // 64x16 tiles, 288 blocks (~2/SM)
    cudaFuncSetAttribute(conv1_gelu_kernel,
                         cudaFuncAttributeMaxDynamicSharedMemorySize, CONV_SMEM);
    conv1_gelu_kernel<<<g1, CTH, CONV_SMEM>>>(x, w1);

    // fuse
    const int smem = (NPIX + PAD) * (int)sizeof(float);
    cudaFuncSetAttribute(fuse_kernel, cudaFuncAttributeMaxDynamicSharedMemorySize, smem);
    fuse_kernel<<<NB * CIN * 2, 768, smem>>>(x, w2, b2, ls, (float*)d_out);
}

// round 17
// speedup vs baseline: 1.2560x; 1.2560x over previous
#include <cuda_runtime.h>
#include <math.h>

#define HH   192
#define WW   192
#define CIN  64
#define SHC  8
#define NB   8
#define NPIX (HH*WW)

typedef unsigned long long ull;

// h = gelu(conv1(x)), PIXEL-MAJOR: [b][pix][8 sh-channels] (9.4 MB)
__device__ float g_h[(size_t)NB * NPIX * SHC];
// x repacked as bf16 ic-pairs: [b][icpair 0..31][pix] word = (ic 2p lo, ic 2p+1 hi)
__device__ unsigned g_xbf[(size_t)NB * (CIN / 2) * NPIX];

__device__ __forceinline__ void cp_async4(void* dst, const void* src) {
    unsigned s = (unsigned)__cvta_generic_to_shared(dst);
    asm volatile("cp.async.ca.shared.global [%0], [%1], 4;\n" :: "r"(s), "l"(src));
}
__device__ __forceinline__ float fsqrt_approx(float v) {
    float r; asm("sqrt.approx.f32 %0, %1;" : "=f"(r) : "f"(v)); return r;
}
__device__ __forceinline__ unsigned bf16pack(float lo, float hi) {
    unsigned r; asm("cvt.rn.bf16x2.f32 %0, %1, %2;" : "=r"(r) : "f"(hi), "f"(lo)); return r;
}
// ---- f32x2 packed helpers (fuse) ----
__device__ __forceinline__ ull ffma2(ull a, ull b, ull c) {
    ull r; asm("fma.rn.f32x2 %0, %1, %2, %3;" : "=l"(r) : "l"(a), "l"(b), "l"(c)); return r;
}
__device__ __forceinline__ ull dup2(float v) {
    ull r; asm("mov.b64 %0, {%1, %1};" : "=l"(r) : "f"(v)); return r;
}
__device__ __forceinline__ ull pack2(float lo, float hi) {
    ull r; asm("mov.b64 %0, {%1, %2};" : "=l"(r) : "f"(lo), "f"(hi)); return r;
}
__device__ __forceinline__ void unpack2(ull v, float& lo, float& hi) {
    asm("mov.b64 {%0, %1}, %2;" : "=f"(lo), "=f"(hi) : "l"(v));
}

// ---------------------------------------------------------------------------
// Kernel 0: repack x fp32 planes -> bf16 ic-pair words.
// R17: 2 quad-iterations per thread (4 LDG.128 in flight) for DRAM latency
// coverage (prepack was 61.8% DRAM with issue 16.8% = MLP-starved).
// ---------------------------------------------------------------------------
__global__ void __launch_bounds__(256, 1)
prepack_kernel(const float* __restrict__ x)
{
    const size_t nquads = (size_t)NB * (CIN / 2) * (NPIX / 4);
    size_t gi0 = ((size_t)blockIdx.x * 256 + threadIdx.x) * 2;   // 2 quads/thread

    const float4* e0;
    const float4* o0;
    const float4* e1;
    const float4* o1;
    uint4* d0;
    uint4* d1;
    float4 ev0, ov0, ev1, ov1;

    {
        size_t gi = gi0;
        int pixq = (int)(gi % (NPIX / 4));
        int bp   = (int)(gi / (NPIX / 4));
        int p    = bp & 31;
        int b    = bp >> 5;
        e0 = reinterpret_cast<const float4*>(x + ((size_t)b * CIN + 2 * p) * NPIX) + pixq;
        o0 = reinterpret_cast<const float4*>(x + ((size_t)b * CIN + 2 * p + 1) * NPIX) + pixq;
        d0 = reinterpret_cast<uint4*>(g_xbf + (size_t)bp * NPIX) + pixq;
    }
    {
        size_t gi = gi0 + 1;
        int pixq = (int)(gi % (NPIX / 4));
        int bp   = (int)(gi / (NPIX / 4));
        int p    = bp & 31;
        int b    = bp >> 5;
        e1 = reinterpret_cast<const float4*>(x + ((size_t)b * CIN + 2 * p) * NPIX) + pixq;
        o1 = reinterpret_cast<const float4*>(x + ((size_t)b * CIN + 2 * p + 1) * NPIX) + pixq;
        d1 = reinterpret_cast<uint4*>(g_xbf + (size_t)bp * NPIX) + pixq;
    }

    // issue all 4 loads back-to-back (MLP=4), then pack+store
    ev0 = *e0; ov0 = *o0; ev1 = *e1; ov1 = *o1;

    uint4 w0, w1;
    w0.x = bf16pack(ev0.x, ov0.x);
    w0.y = bf16pack(ev0.y, ov0.y);
    w0.z = bf16pack(ev0.z, ov0.z);
    w0.w = bf16pack(ev0.w, ov0.w);
    w1.x = bf16pack(ev1.x, ov1.x);
    w1.y = bf16pack(ev1.y, ov1.y);
    w1.z = bf16pack(ev1.z, ov1.z);
    w1.w = bf16pack(ev1.w, ov1.w);
    *d0 = w0;
    *d1 = w1;
}

// ---------------------------------------------------------------------------
// Kernel 1: EXACT R15 conv (measured 32.4us): bf16 m16n8k16 mma, 512 thr,
// tile 64x32, 2-stage cp.async double buffer of bf16-pair planes.
// ---------------------------------------------------------------------------
#define PS     2248                    // pair-plane stride in words (8 mod 32)
#define PROWS  34
#define PCOLS  66
#define PLANES 8                       // 8 ic-pair planes per icg (= 16 ics)
#define DBUF   (PLANES * PS)
#define WOFF   (2 * DBUF)
#define NWSM   (4 * 9 * 8 * 8)         // [icg][tap][kpair][oc] words
#define CONV_SMEM ((2 * DBUF + NWSM) * 4)
#define CTH    512

__global__ void __launch_bounds__(CTH, 1)
conv1_gelu_kernel(const float* __restrict__ w1)
{
    extern __shared__ unsigned sm_u[];
    unsigned* dsm = sm_u;              // [2][PLANES*PS] bf16x2 words
    unsigned* wsm = sm_u + WOFF;       // [icg][tap][kpair][oc] bf16x2 words

    const int tid   = threadIdx.x;
    const int b     = blockIdx.z;
    const int tileX = blockIdx.x * 64;
    const int tileY = blockIdx.y * 32;

    for (int i = tid; i < NWSM; i += CTH) {
        int oc  = i & 7;
        int kp  = (i >> 3) & 7;
        int tap = (i >> 6) % 9;
        int icg = i / (9 * 64);
        int ic  = icg * 16 + 2 * kp;
        wsm[i] = bf16pack(w1[(oc * CIN + ic) * 9 + tap],
                          w1[(oc * CIN + ic + 1) * 9 + tap]);
    }

    const unsigned* xpb = g_xbf + (size_t)b * (CIN / 2) * NPIX;

    auto load_group = [&](int icg, int buf) {
        for (int i = tid; i < PLANES * PROWS * PCOLS; i += CTH) {
            int p   = i / (PROWS * PCOLS);
            int rem = i - p * (PROWS * PCOLS);
            int r   = rem / PCOLS;
            int cc  = rem - r * PCOLS;
            int gy  = tileY - 1 + r;
            int gx  = tileX - 1 + cc;
            unsigned* dp = dsm + buf * DBUF + p * PS + r * PCOLS + cc;
            if ((unsigned)gy < (unsigned)HH && (unsigned)gx < (unsigned)WW)
                cp_async4(dp, xpb + (size_t)(icg * PLANES + p) * NPIX + gy * WW + gx);
            else
                *dp = 0u;
        }
    };

    load_group(0, 0);
    asm volatile("cp.async.commit_group;\n");

    const int lane = tid & 31;
    const int wrp  = tid >> 5;        // 0..15
    const int g    = lane >> 2;
    const int t4   = lane & 3;

    float acc[8][4];
    #pragma unroll
    for (int m = 0; m < 8; m++)
        #pragma unroll
        for (int e = 0; e < 4; e++) acc[m][e] = 0.f;

    for (int icg = 0; icg < 4; icg++) {
        if (icg < 3) asm volatile("cp.async.wait_group 1;\n");
        else         asm volatile("cp.async.wait_group 0;\n");
        __syncthreads();
        if (icg + 1 < 4) {
            load_group(icg + 1, (icg + 1) & 1);
            asm volatile("cp.async.commit_group;\n");
        }

        const unsigned* A0 = dsm + (icg & 1) * DBUF + t4 * PS + g;
        const unsigned* A1 = A0 + 4 * PS;
        const unsigned* wg = wsm + (icg * 9) * 64;

        #pragma unroll
        for (int tap = 0; tap < 9; tap++) {
            const int ky = tap / 3, kx = tap % 3;
            unsigned b0 = wg[tap * 64 + t4 * 8 + g];
            unsigned b1 = wg[tap * 64 + (t4 + 4) * 8 + g];

            #pragma unroll
            for (int r = 0; r < 2; r++) {
                const int rowoff = (2 * wrp + r + ky) * PCOLS + kx;
                #pragma unroll
                for (int q = 0; q < 4; q++) {
                    const int off = rowoff + 16 * q;
                    unsigned a0 = A0[off];
                    unsigned a1 = A0[off + 8];
                    unsigned a2 = A1[off];
                    unsigned a3 = A1[off + 8];
                    float* d = acc[r * 4 + q];
                    asm volatile(
                        "mma.sync.aligned.m16n8k16.row.col.f32.bf16.bf16.f32 "
                        "{%0,%1,%2,%3}, {%4,%5,%6,%7}, {%8,%9}, {%0,%1,%2,%3};"
                        : "+f"(d[0]), "+f"(d[1]), "+f"(d[2]), "+f"(d[3])
                        : "r"(a0), "r"(a1), "r"(a2), "r"(a3), "r"(b0), "r"(b1));
                }
            }
        }
    }

    const float inv_sqrt2 = 0.70710678118654752f;
    #pragma unroll
    for (int r = 0; r < 2; r++) {
        const int gy = tileY + 2 * wrp + r;
        #pragma unroll
        for (int q = 0; q < 4; q++) {
            const float* d = acc[r * 4 + q];
            const int px0 = tileX + 16 * q + g;
            float* hp0 = g_h + ((size_t)b * NPIX + (size_t)gy * WW + px0) * SHC + 2 * t4;
            float2 o;
            float u;
            u = d[0]; o.x = 0.5f * u * (1.f + erff(u * inv_sqrt2));
            u = d[1]; o.y = 0.5f * u * (1.f + erff(u * inv_sqrt2));
            *reinterpret_cast<float2*>(hp0) = o;
            u = d[2]; o.x = 0.5f * u * (1.f + erff(u * inv_sqrt2));
            u = d[3]; o.y = 0.5f * u * (1.f + erff(u * inv_sqrt2));
            *reinterpret_cast<float2*>(hp0 + 8 * SHC) = o;
        }
    }
}

// ---------------------------------------------------------------------------
// Kernel 2: EXACT R10/R12 fuse (measured best: 119.2us). PROTECTED.
// ---------------------------------------------------------------------------
#define PAD 200

__global__ void __launch_bounds__(768, 1)
fuse_kernel(const float* __restrict__ x, const float* __restrict__ w2,
            const float* __restrict__ b2, const float* __restrict__ lsc,
            float* __restrict__ out)
{
    extern __shared__ float img[];           // NPIX + PAD floats
    const int tid  = threadIdx.x;
    const int bc   = blockIdx.x >> 1;
    const int half = blockIdx.x & 1;
    const int c    = bc & 63;

    const float4* src  = reinterpret_cast<const float4*>(x + (size_t)bc * NPIX);
    float4*       dst4 = reinterpret_cast<float4*>(img);
    #pragma unroll 4
    for (int i = tid; i < NPIX / 4; i += 768) dst4[i] = src[i];
    if (tid < PAD / 4)
        reinterpret_cast<float4*>(img + NPIX)[tid] = make_float4(0.f, 0.f, 0.f, 0.f);

    const float PXS = 9.55f;                 // 0.1 * 95.5
    ull w01[8], w23[8];
    #pragma unroll
    for (int s = 0; s < 8; s++) {
        w01[s] = pack2(__ldg(&w2[(4 * c + 0) * 8 + s]),
                       __ldg(&w2[(4 * c + 1) * 8 + s]) * PXS);
        w23[s] = pack2(__ldg(&w2[(4 * c + 2) * 8 + s]) * PXS,
                       __ldg(&w2[(4 * c + 3) * 8 + s]));
    }
    const ull bias01 = pack2(__ldg(&b2[4 * c + 0]), __ldg(&b2[4 * c + 1]) * PXS);
    const ull bias23 = pack2(__ldg(&b2[4 * c + 2]) * PXS, __ldg(&b2[4 * c + 3]));

    const float esc   = expf(__ldg(lsc));
    const float esc4  = 0.25f * esc;
    const float esc01 = 0.1f  * esc;
    const float* hb = g_h + (size_t)(bc >> 6) * NPIX * SHC;
    float* ob = out + (size_t)bc * NPIX;

    const float step = 2.0f / 191.0f;

    const int rphase = tid / 192;            // 0..3
    const int xi     = tid - rphase * 192;   // 0..191
    const float gxpix = (fmaf((float)xi, step, -1.0f) + 1.0f) * 95.5f;
    const int y0     = half * 96 + rphase;

    __syncthreads();

    #pragma unroll 1
    for (int k = 0; k < 12; k++) {
        const int yiA  = y0 + 4 * k;
        const int idxA = yiA * WW + xi;

        int   idx[2]   = { idxA, idxA + 48 * WW };
        float gypix[2] = { (fmaf((float)yiA,        step, -1.0f) + 1.0f) * 95.5f,
                           (fmaf((float)(yiA + 48), step, -1.0f) + 1.0f) * 95.5f };

        float4 h0[2], h1[2];
        #pragma unroll
        for (int j = 0; j < 2; j++) {
            const float4* hp = reinterpret_cast<const float4*>(hb + (size_t)idx[j] * SHC);
            h0[j] = hp[0];
            h1[j] = hp[1];
        }

        float s95[2], dxp[2], dyp[2], cvv[2];
        #pragma unroll
        for (int j = 0; j < 2; j++) {
            ull a01 = bias01, a23 = bias23;
            ull d;
            d = dup2(h0[j].x); a01 = ffma2(d, w01[0], a01); a23 = ffma2(d, w23[0], a23);
            d = dup2(h0[j].y); a01 = ffma2(d, w01[1], a01); a23 = ffma2(d, w23[1], a23);
            d = dup2(h0[j].z); a01 = ffma2(d, w01[2], a01); a23 = ffma2(d, w23[2], a23);
            d = dup2(h0[j].w); a01 = ffma2(d, w01[3], a01); a23 = ffma2(d, w23[3], a23);
            d = dup2(h1[j].x); a01 = ffma2(d, w01[4], a01); a23 = ffma2(d, w23[4], a23);
            d = dup2(h1[j].y); a01 = ffma2(d, w01[5], a01); a23 = ffma2(d, w23[5], a23);
            d = dup2(h1[j].z); a01 = ffma2(d, w01[6], a01); a23 = ffma2(d, w23[6], a23);
            d = dup2(h1[j].w); a01 = ffma2(d, w01[7], a01); a23 = ffma2(d, w23[7], a23);
            float a, bxp, byp, cv;
            unpack2(a01, a, bxp);
            unpack2(a23, byp, cv);

            float t  = __expf(-fabsf(a));
            float sp = fmaxf(a, 0.f) + __logf(1.0f + t);
            s95[j] = fsqrt_approx(fmaf(sp, 912.025f, 9.12025e-5f));
            dxp[j] = bxp;
            dyp[j] = byp;
            cvv[j] = fminf(fmaxf(cv, -5.f), 5.f);
        }

        #pragma unroll
        for (int j = 0; j < 2; j++) {
            float px3  = gxpix    + dxp[j];
            float px1  = px3      + s95[j];
            float px2  = px3      - s95[j];
            float py12 = gypix[j] + dyp[j];
            float py3  = py12     + s95[j];
            float py4  = py12     - s95[j];

            float pyc = fminf(fmaxf(py12, 0.f), 191.f);
            float y0f = floorf(pyc);
            float wy  = pyc - y0f;

            float pxc1 = fminf(fmaxf(px1, 0.f), 191.f);
            float x0f1 = floorf(pxc1);
            float wx1  = pxc1 - x0f1;
            int   o1   = (int)fmaf(y0f, 192.f, x0f1);
            float v00 = img[o1],       v01 = img[o1 + 1];
            float v10 = img[o1 + 192], v11 = img[o1 + 193];
            float top = fmaf(v01 - v00, wx1, v00);
            float bot = fmaf(v11 - v10, wx1, v10);
            float u1  = fmaf(bot - top, wy, top);

            float pxc2 = fminf(fmaxf(px2, 0.f), 191.f);
            float x0f2 = floorf(pxc2);
            float wx2  = pxc2 - x0f2;
            int   o2   = (int)fmaf(y0f, 192.f, x0f2);
            v00 = img[o2];       v01 = img[o2 + 1];
            v10 = img[o2 + 192]; v11 = img[o2 + 193];
            top = fmaf(v01 - v00, wx2, v00);
            bot = fmaf(v11 - v10, wx2, v10);
            float u2 = fmaf(bot - top, wy, top);

            float pxc3 = fminf(fmaxf(px3, 0.f), 191.f);
            float x0f3 = floorf(pxc3);
            float wx3  = pxc3 - x0f3;

            float pyc3 = fminf(fmaxf(py3, 0.f), 191.f);
            float y0f3 = floorf(pyc3);
            float wy3  = pyc3 - y0f3;
            int   o3   = (int)fmaf(y0f3, 192.f, x0f3);
            v00 = img[o3];       v01 = img[o3 + 1];
            v10 = img[o3 + 192]; v11 = img[o3 + 193];
            top = fmaf(v01 - v00, wx3, v00);
            bot = fmaf(v11 - v10, wx3, v10);
            float u3 = fmaf(bot - top, wy3, top);

            float pyc4 = fminf(fmaxf(py4, 0.f), 191.f);
            float y0f4 = floorf(pyc4);
            float wy4  = pyc4 - y0f4;
            int   o4   = (int)fmaf(y0f4, 192.f, x0f3);
            v00 = img[o4];       v01 = img[o4 + 1];
            v10 = img[o4 + 192]; v11 = img[o4 + 193];
            top = fmaf(v01 - v00, wx3, v00);
            bot = fmaf(v11 - v10, wx3, v10);
            float u4 = fmaf(bot - top, wy4, top);

            float usum = (u1 + u2) + (u3 + u4);
            float xv   = img[idx[j]];
            ob[idx[j]] = fmaf(esc4, usum, esc01 * cvv[j] * xv);
        }
    }
}

// ---------------------------------------------------------------------------
extern "C" void kernel_launch(void* const* d_in, const int* in_sizes, int n_in,
                              void* d_out, int out_size)
{
    const float *x = nullptr, *w1 = nullptr, *w2 = nullptr, *b2 = nullptr, *ls = nullptr;
    for (int i = 0; i < n_in; i++) {
        switch (in_sizes[i]) {
            case NB * CIN * NPIX: x  = (const float*)d_in[i]; break;
            case SHC * CIN * 9:   w1 = (const float*)d_in[i]; break;
            case 4 * CIN * SHC:   w2 = (const float*)d_in[i]; break;
            case 4 * CIN:         b2 = (const float*)d_in[i]; break;
            case 1:               ls = (const float*)d_in[i]; break;
            default: break;
        }
    }

    // 0) repack x -> bf16 ic-pair words (2 quads/thread)
    {
        size_t nquads = (size_t)NB * (CIN / 2) * (NPIX / 4);   // 2,359,296
        int blocks = (int)((nquads / 2 + 255) / 256);
        prepack_kernel<<<blocks, 256>>>(x);
    }

    // 1) conv via bf16 mma (exact R15)
    dim3 g1(3, 6, NB);
    cudaFuncSetAttribute(conv1_gelu_kernel,
                         cudaFuncAttributeMaxDynamicSharedMemorySize, CONV_SMEM);
    conv1_gelu_kernel<<<g1, CTH, CONV_SMEM>>>(w1);

    // 2) fuse (exact R12)
    const int smem = (NPIX + PAD) * (int)sizeof(float);
    cudaFuncSetAttribute(fuse_kernel, cudaFuncAttributeMaxDynamicSharedMemorySize, smem);
    fuse_kernel<<<NB * CIN * 2, 768, smem>>>(x, w2, b2, ls, (float*)d_out);
}